// round 2
// baseline (speedup 1.0000x reference)
#include <cuda_runtime.h>
#include <math.h>

// Problem constants (fixed by the dataset)
#define N_NODES 40000
#define N_EDGES 640000
#define DIM     128
#define OUTD    64
#define NGRAPH  64

// ---------------- device scratch (no allocation allowed) ----------------
__device__ float g_t[N_NODES * DIM];     // GEMM output (pre-aggregation features)
__device__ float g_h[N_NODES * DIM];     // layer output (post relu)
__device__ int   g_cnt[N_NODES];         // in-degree counts
__device__ int   g_rowptr[N_NODES + 1];  // CSR row pointers (by dst)
__device__ int   g_cursor[N_NODES];      // scatter cursors
__device__ int   g_col[N_EDGES];         // CSR col (src) indices
__device__ float g_dinv[N_NODES];        // 1/sqrt(deg+1)
__device__ float g_gsum[NGRAPH * DIM];   // pooled sums
__device__ int   g_gcnt[NGRAPH];         // nodes per graph
__device__ int   g_is64;                 // 1 if indices are int64, 0 if int32

// Uniform index load honoring detected dtype.
__device__ __forceinline__ int load_idx(const void* p, int i) {
    if (g_is64) return (int)((const long long*)p)[i];
    return ((const int*)p)[i];
}

// ---------------- dtype detection (single thread) ----------------
__global__ void detect_kernel(const void* __restrict__ ei) {
    // Interpret first 16 entries as int64. True int64 indices are all in
    // [0, N_NODES). If data is actually int32, packed pairs give huge values.
    const long long* p = (const long long*)ei;
    int ok = 1;
    #pragma unroll
    for (int i = 0; i < 16; ++i) {
        long long v = p[i];
        if (v < 0 || v >= N_NODES) ok = 0;
    }
    g_is64 = ok;
}

// ---------------- init: zero counters ----------------
__global__ void init_kernel() {
    int i = blockIdx.x * blockDim.x + threadIdx.x;
    if (i < N_NODES) g_cnt[i] = 0;
    if (i < NGRAPH * DIM) g_gsum[i] = 0.f;
    if (i < NGRAPH) g_gcnt[i] = 0;
}

// ---------------- degree count (in-degree at dst) ----------------
__global__ void count_kernel(const void* __restrict__ ei) {
    int e = blockIdx.x * blockDim.x + threadIdx.x;
    if (e < N_EDGES) {
        int dst = load_idx(ei, N_EDGES + e);
        atomicAdd(&g_cnt[dst], 1);
    }
}

// ---------------- exclusive scan over counts (single block, warp scans) ----
__global__ void scan_kernel() {
    __shared__ int wsum[32];
    __shared__ int carry;
    int tid = threadIdx.x, lane = tid & 31, w = tid >> 5;
    if (tid == 0) { carry = 0; g_rowptr[0] = 0; }
    __syncthreads();
    for (int base = 0; base < N_NODES; base += 1024) {
        int i = base + tid;
        int v = (i < N_NODES) ? g_cnt[i] : 0;
        int incl = v;
        #pragma unroll
        for (int off = 1; off < 32; off <<= 1) {
            int t = __shfl_up_sync(0xffffffffu, incl, off);
            if (lane >= off) incl += t;
        }
        if (lane == 31) wsum[w] = incl;
        __syncthreads();
        if (w == 0) {
            int s = wsum[lane];
            #pragma unroll
            for (int off = 1; off < 32; off <<= 1) {
                int t = __shfl_up_sync(0xffffffffu, s, off);
                if (lane >= off) s += t;
            }
            wsum[lane] = s;
        }
        __syncthreads();
        int pref = (w > 0) ? wsum[w - 1] : 0;
        int inclTot = incl + pref + carry;
        if (i < N_NODES) {
            g_rowptr[i + 1] = inclTot;
            g_cursor[i] = inclTot - v;
            g_dinv[i] = rsqrtf((float)v + 1.0f);
        }
        __syncthreads();
        if (tid == 1023) carry = inclTot;
        __syncthreads();
    }
}

// ---------------- CSR fill: scatter src into per-dst slots ----------------
__global__ void fill_kernel(const void* __restrict__ ei) {
    int e = blockIdx.x * blockDim.x + threadIdx.x;
    if (e < N_EDGES) {
        int src = load_idx(ei, e);
        int dst = load_idx(ei, N_EDGES + e);
        int pos = atomicAdd(&g_cursor[dst], 1);
        g_col[pos] = src;
    }
}

// ---------------- SGEMM: g_t = A(40000x128) @ W(128x128) ----------------
// Block tile 64x128, 128 threads, 8x8 microtile per thread.
__global__ __launch_bounds__(128) void gemm_kernel(const float* __restrict__ Ain,
                                                   const float* __restrict__ W) {
    const float* A = Ain ? Ain : g_h;
    __shared__ float As[32][68];    // [k][m], padded (68*4B = 16B-aligned rows)
    __shared__ float Bs[32][128];   // [k][n]

    int tid  = threadIdx.x;
    int tcol = tid & 15;   // 16 * TN(8) = 128 cols
    int trow = tid >> 4;   // 8  * TM(8) = 64 rows
    int row0 = blockIdx.x * 64;

    float acc[8][8];
    #pragma unroll
    for (int i = 0; i < 8; ++i)
        #pragma unroll
        for (int j = 0; j < 8; ++j) acc[i][j] = 0.f;

    for (int kt = 0; kt < 4; ++kt) {
        // load A tile (64 rows x 32 k), transposed into As[k][m]
        {
            int m  = tid >> 1;           // 0..63
            int k0 = (tid & 1) * 16;     // 0 or 16
            const float* ap = &A[(row0 + m) * DIM + kt * 32 + k0];
            #pragma unroll
            for (int q = 0; q < 4; ++q) {
                float4 a = *(const float4*)(ap + q * 4);
                As[k0 + q * 4 + 0][m] = a.x;
                As[k0 + q * 4 + 1][m] = a.y;
                As[k0 + q * 4 + 2][m] = a.z;
                As[k0 + q * 4 + 3][m] = a.w;
            }
        }
        // load B tile (32 k x 128 n)
        #pragma unroll
        for (int i = 0; i < 8; ++i) {
            int f  = tid + i * 128;      // 0..1023 float4 slots
            int kk = f >> 5;
            int nn = (f & 31) * 4;
            *(float4*)&Bs[kk][nn] = *(const float4*)&W[(kt * 32 + kk) * DIM + nn];
        }
        __syncthreads();

        #pragma unroll
        for (int k = 0; k < 32; ++k) {
            float4 a0 = *(const float4*)&As[k][trow * 8];
            float4 a1 = *(const float4*)&As[k][trow * 8 + 4];
            float4 b0 = *(const float4*)&Bs[k][tcol * 8];
            float4 b1 = *(const float4*)&Bs[k][tcol * 8 + 4];
            float av[8] = {a0.x, a0.y, a0.z, a0.w, a1.x, a1.y, a1.z, a1.w};
            float bv[8] = {b0.x, b0.y, b0.z, b0.w, b1.x, b1.y, b1.z, b1.w};
            #pragma unroll
            for (int i = 0; i < 8; ++i)
                #pragma unroll
                for (int j = 0; j < 8; ++j)
                    acc[i][j] = fmaf(av[i], bv[j], acc[i][j]);
        }
        __syncthreads();
    }

    #pragma unroll
    for (int i = 0; i < 8; ++i) {
        int r = row0 + trow * 8 + i;
        float4 c0 = make_float4(acc[i][0], acc[i][1], acc[i][2], acc[i][3]);
        float4 c1 = make_float4(acc[i][4], acc[i][5], acc[i][6], acc[i][7]);
        *(float4*)&g_t[r * DIM + tcol * 8]     = c0;
        *(float4*)&g_t[r * DIM + tcol * 8 + 4] = c1;
    }
}

// ---------------- aggregation: g_h = relu(sym-norm agg(g_t) + dinv^2*g_t + b)
__global__ __launch_bounds__(128) void agg_kernel(const float* __restrict__ bias) {
    int i = blockIdx.x;
    int tid = threadIdx.x;
    float di = g_dinv[i];
    float acc = di * di * g_t[i * DIM + tid];
    int s = g_rowptr[i], e = g_rowptr[i + 1];

    __shared__ int   ssrc[128];
    __shared__ float sw[128];

    for (int base = s; base < e; base += 128) {
        int n = min(128, e - base);
        if (tid < n) {
            int c = g_col[base + tid];
            ssrc[tid] = c;
            sw[tid]   = g_dinv[c] * di;
        }
        __syncthreads();
        int j = 0;
        for (; j + 8 <= n; j += 8) {
            float v0 = g_t[ssrc[j + 0] * DIM + tid];
            float v1 = g_t[ssrc[j + 1] * DIM + tid];
            float v2 = g_t[ssrc[j + 2] * DIM + tid];
            float v3 = g_t[ssrc[j + 3] * DIM + tid];
            float v4 = g_t[ssrc[j + 4] * DIM + tid];
            float v5 = g_t[ssrc[j + 5] * DIM + tid];
            float v6 = g_t[ssrc[j + 6] * DIM + tid];
            float v7 = g_t[ssrc[j + 7] * DIM + tid];
            acc = fmaf(sw[j + 0], v0, acc);
            acc = fmaf(sw[j + 1], v1, acc);
            acc = fmaf(sw[j + 2], v2, acc);
            acc = fmaf(sw[j + 3], v3, acc);
            acc = fmaf(sw[j + 4], v4, acc);
            acc = fmaf(sw[j + 5], v5, acc);
            acc = fmaf(sw[j + 6], v6, acc);
            acc = fmaf(sw[j + 7], v7, acc);
        }
        for (; j < n; ++j)
            acc = fmaf(sw[j], g_t[ssrc[j] * DIM + tid], acc);
        __syncthreads();
    }
    g_h[i * DIM + tid] = fmaxf(acc + bias[tid], 0.f);
}

// ---------------- mean pool (batch is sorted): segmented sums -------------
__global__ __launch_bounds__(128) void pool_kernel(const void* __restrict__ batch) {
    int n0  = blockIdx.x * 64;      // 625 blocks * 64 nodes = 40000
    int tid = threadIdx.x;
    float acc = 0.f;
    int c = 0;
    int cur = load_idx(batch, n0);
    for (int n = n0; n < n0 + 64; ++n) {
        int g = load_idx(batch, n);
        if (g != cur) {
            atomicAdd(&g_gsum[cur * DIM + tid], acc);
            if (tid == 0) atomicAdd(&g_gcnt[cur], c);
            acc = 0.f; c = 0; cur = g;
        }
        acc += g_h[n * DIM + tid];
        ++c;
    }
    atomicAdd(&g_gsum[cur * DIM + tid], acc);
    if (tid == 0) atomicAdd(&g_gcnt[cur], c);
}

// ---------------- final: mean -> linear -> L2 normalize -------------------
__global__ __launch_bounds__(64) void final_kernel(const float* __restrict__ Wl,
                                                   const float* __restrict__ bl,
                                                   float* __restrict__ out) {
    int g = blockIdx.x, o = threadIdx.x;  // 64 graphs x 64 outputs
    __shared__ float mean[DIM];
    __shared__ float red[OUTD];
    float cn = fmaxf((float)g_gcnt[g], 1.f);
    mean[o]      = g_gsum[g * DIM + o] / cn;
    mean[o + 64] = g_gsum[g * DIM + o + 64] / cn;
    __syncthreads();
    float acc = bl[o];
    #pragma unroll
    for (int h = 0; h < DIM; ++h)
        acc = fmaf(mean[h], Wl[h * OUTD + o], acc);
    red[o] = acc * acc;
    __syncthreads();
    for (int s = 32; s > 0; s >>= 1) {
        if (o < s) red[o] += red[o + s];
        __syncthreads();
    }
    float nrm = sqrtf(red[0]);
    out[g * OUTD + o] = acc / fmaxf(nrm, 1e-12f);
}

// ---------------- launch ----------------
extern "C" void kernel_launch(void* const* d_in, const int* in_sizes, int n_in,
                              void* d_out, int out_size) {
    const float* x     = (const float*)d_in[0];
    const float* W1    = (const float*)d_in[1];
    const float* b1    = (const float*)d_in[2];
    const float* W2    = (const float*)d_in[3];
    const float* b2    = (const float*)d_in[4];
    const float* Wl    = (const float*)d_in[5];
    const float* bl    = (const float*)d_in[6];
    const void*  ei    = d_in[7];
    const void*  batch = d_in[8];
    float* out = (float*)d_out;

    detect_kernel<<<1, 1>>>(ei);
    init_kernel<<<(N_NODES + 255) / 256, 256>>>();
    count_kernel<<<(N_EDGES + 255) / 256, 256>>>(ei);
    scan_kernel<<<1, 1024>>>();
    fill_kernel<<<(N_EDGES + 255) / 256, 256>>>(ei);

    // layer 1
    gemm_kernel<<<N_NODES / 64, 128>>>(x, W1);
    agg_kernel<<<N_NODES, 128>>>(b1);
    // layer 2
    gemm_kernel<<<N_NODES / 64, 128>>>(nullptr, W2);
    agg_kernel<<<N_NODES, 128>>>(b2);

    pool_kernel<<<N_NODES / 64, 128>>>(batch);
    final_kernel<<<NGRAPH, OUTD>>>(Wl, bl, out);
}

// round 3
// speedup vs baseline: 1.1144x; 1.1144x over previous
#include <cuda_runtime.h>
#include <math.h>

// Problem constants (fixed by the dataset)
#define N_NODES 40000
#define N_EDGES 640000
#define DIM     128
#define OUTD    64
#define NGRAPH  64
#define SCAN_B  40            // ceil(40000/1024)

// ---------------- device scratch (no allocation allowed) ----------------
__device__ float g_t[N_NODES * DIM];     // GEMM output (pre-aggregation features)
__device__ float g_h[N_NODES * DIM];     // layer output (post relu)
__device__ int   g_cnt[N_NODES];         // in-degree counts
__device__ int   g_rowptr[N_NODES + 1];  // CSR row pointers (by dst)
__device__ int   g_cursor[N_NODES];      // scatter cursors
__device__ int   g_col[N_EDGES];         // CSR col (src) indices
__device__ float g_dinv[N_NODES];        // 1/sqrt(deg+1)
__device__ float g_gsum[NGRAPH * DIM];   // pooled sums
__device__ int   g_gcnt[NGRAPH];         // nodes per graph
__device__ int   g_is64;                 // 1 if indices are int64, 0 if int32
__device__ int   g_bsum[SCAN_B];         // per-block sums for scan
__device__ int   g_boff[SCAN_B];         // exclusive block offsets

// Uniform index load honoring detected dtype.
__device__ __forceinline__ int load_idx(const void* p, int i) {
    if (g_is64) return (int)((const long long*)p)[i];
    return ((const int*)p)[i];
}

// ---------------- dtype detection (single thread) ----------------
__global__ void detect_kernel(const void* __restrict__ ei) {
    const long long* p = (const long long*)ei;
    int ok = 1;
    #pragma unroll
    for (int i = 0; i < 16; ++i) {
        long long v = p[i];
        if (v < 0 || v >= N_NODES) ok = 0;
    }
    g_is64 = ok;
}

// ---------------- init: zero counters ----------------
__global__ void init_kernel() {
    int i = blockIdx.x * blockDim.x + threadIdx.x;
    if (i < N_NODES) g_cnt[i] = 0;
    if (i < NGRAPH * DIM) g_gsum[i] = 0.f;
    if (i < NGRAPH) g_gcnt[i] = 0;
}

// ---------------- degree count (in-degree at dst) ----------------
__global__ __launch_bounds__(512) void count_kernel(const void* __restrict__ ei) {
    int e = blockIdx.x * blockDim.x + threadIdx.x;
    if (e < N_EDGES) {
        int dst = load_idx(ei, N_EDGES + e);
        atomicAdd(&g_cnt[dst], 1);
    }
}

// ---------------- scan pass 1: per-block sums (40 blocks x 1024) ----------
__global__ __launch_bounds__(1024) void scan1_kernel() {
    __shared__ int wsum[32];
    int tid = threadIdx.x, lane = tid & 31, w = tid >> 5;
    int i = blockIdx.x * 1024 + tid;
    int v = (i < N_NODES) ? g_cnt[i] : 0;
    int s = v;
    #pragma unroll
    for (int off = 16; off > 0; off >>= 1)
        s += __shfl_down_sync(0xffffffffu, s, off);
    if (lane == 0) wsum[w] = s;
    __syncthreads();
    if (w == 0) {
        int t = wsum[lane];
        #pragma unroll
        for (int off = 16; off > 0; off >>= 1)
            t += __shfl_down_sync(0xffffffffu, t, off);
        if (lane == 0) g_bsum[blockIdx.x] = t;
    }
}

// ---------------- scan pass 2: exclusive scan of 40 block sums -----------
__global__ void scan2_kernel() {
    int tid = threadIdx.x;  // 64 threads, one warp pair; use warp 0+1 scan
    int v = (tid < SCAN_B) ? g_bsum[tid] : 0;
    // inclusive scan over 64 lanes via two warp scans in smem
    __shared__ int tmp[64];
    int lane = tid & 31, w = tid >> 5;
    int incl = v;
    #pragma unroll
    for (int off = 1; off < 32; off <<= 1) {
        int t = __shfl_up_sync(0xffffffffu, incl, off);
        if (lane >= off) incl += t;
    }
    tmp[tid] = incl;
    __syncthreads();
    int add = (w == 1) ? tmp[31] : 0;
    int excl = incl - v + add;
    if (tid < SCAN_B) g_boff[tid] = excl;
}

// ---------------- scan pass 3: block scan + offset, write CSR meta --------
__global__ __launch_bounds__(1024) void scan3_kernel() {
    __shared__ int wsum[32];
    int tid = threadIdx.x, lane = tid & 31, w = tid >> 5;
    int i = blockIdx.x * 1024 + tid;
    int v = (i < N_NODES) ? g_cnt[i] : 0;
    int incl = v;
    #pragma unroll
    for (int off = 1; off < 32; off <<= 1) {
        int t = __shfl_up_sync(0xffffffffu, incl, off);
        if (lane >= off) incl += t;
    }
    if (lane == 31) wsum[w] = incl;
    __syncthreads();
    if (w == 0) {
        int s = wsum[lane];
        #pragma unroll
        for (int off = 1; off < 32; off <<= 1) {
            int t = __shfl_up_sync(0xffffffffu, s, off);
            if (lane >= off) s += t;
        }
        wsum[lane] = s;
    }
    __syncthreads();
    int pref = (w > 0) ? wsum[w - 1] : 0;
    int inclTot = incl + pref + g_boff[blockIdx.x];
    if (i < N_NODES) {
        g_rowptr[i + 1] = inclTot;
        g_cursor[i] = inclTot - v;
        g_dinv[i] = rsqrtf((float)v + 1.0f);
        if (i == 0) g_rowptr[0] = 0;
    }
}

// ---------------- CSR fill: scatter src into per-dst slots ----------------
__global__ __launch_bounds__(512) void fill_kernel(const void* __restrict__ ei) {
    int e = blockIdx.x * blockDim.x + threadIdx.x;
    if (e < N_EDGES) {
        int src = load_idx(ei, e);
        int dst = load_idx(ei, N_EDGES + e);
        int pos = atomicAdd(&g_cursor[dst], 1);
        g_col[pos] = src;
    }
}

// ---------------- SGEMM: g_t = A(40000x128) @ W(128x128) ----------------
// Block tile 64x128, 128 threads, 8x8 microtile per thread.
__global__ __launch_bounds__(128) void gemm_kernel(const float* __restrict__ Ain,
                                                   const float* __restrict__ W) {
    const float* A = Ain ? Ain : g_h;
    __shared__ float As[32][68];    // [k][m], padded
    __shared__ float Bs[32][128];   // [k][n]

    int tid  = threadIdx.x;
    int tcol = tid & 15;   // 16 * TN(8) = 128 cols
    int trow = tid >> 4;   // 8  * TM(8) = 64 rows
    int row0 = blockIdx.x * 64;

    float acc[8][8];
    #pragma unroll
    for (int i = 0; i < 8; ++i)
        #pragma unroll
        for (int j = 0; j < 8; ++j) acc[i][j] = 0.f;

    for (int kt = 0; kt < 4; ++kt) {
        {
            int m  = tid >> 1;
            int k0 = (tid & 1) * 16;
            const float* ap = &A[(row0 + m) * DIM + kt * 32 + k0];
            #pragma unroll
            for (int q = 0; q < 4; ++q) {
                float4 a = *(const float4*)(ap + q * 4);
                As[k0 + q * 4 + 0][m] = a.x;
                As[k0 + q * 4 + 1][m] = a.y;
                As[k0 + q * 4 + 2][m] = a.z;
                As[k0 + q * 4 + 3][m] = a.w;
            }
        }
        #pragma unroll
        for (int i = 0; i < 8; ++i) {
            int f  = tid + i * 128;
            int kk = f >> 5;
            int nn = (f & 31) * 4;
            *(float4*)&Bs[kk][nn] = *(const float4*)&W[(kt * 32 + kk) * DIM + nn];
        }
        __syncthreads();

        #pragma unroll
        for (int k = 0; k < 32; ++k) {
            float4 a0 = *(const float4*)&As[k][trow * 8];
            float4 a1 = *(const float4*)&As[k][trow * 8 + 4];
            float4 b0 = *(const float4*)&Bs[k][tcol * 8];
            float4 b1 = *(const float4*)&Bs[k][tcol * 8 + 4];
            float av[8] = {a0.x, a0.y, a0.z, a0.w, a1.x, a1.y, a1.z, a1.w};
            float bv[8] = {b0.x, b0.y, b0.z, b0.w, b1.x, b1.y, b1.z, b1.w};
            #pragma unroll
            for (int i = 0; i < 8; ++i)
                #pragma unroll
                for (int j = 0; j < 8; ++j)
                    acc[i][j] = fmaf(av[i], bv[j], acc[i][j]);
        }
        __syncthreads();
    }

    #pragma unroll
    for (int i = 0; i < 8; ++i) {
        int r = row0 + trow * 8 + i;
        float4 c0 = make_float4(acc[i][0], acc[i][1], acc[i][2], acc[i][3]);
        float4 c1 = make_float4(acc[i][4], acc[i][5], acc[i][6], acc[i][7]);
        *(float4*)&g_t[r * DIM + tcol * 8]     = c0;
        *(float4*)&g_t[r * DIM + tcol * 8 + 4] = c1;
    }
}

// ---------------- aggregation: g_h = relu(sym-norm agg(g_t) + dinv^2*g_t + b)
__global__ __launch_bounds__(128) void agg_kernel(const float* __restrict__ bias) {
    int i = blockIdx.x;
    int tid = threadIdx.x;
    float di = g_dinv[i];
    float acc = di * di * g_t[i * DIM + tid];
    int s = g_rowptr[i], e = g_rowptr[i + 1];

    __shared__ int   ssrc[128];
    __shared__ float sw[128];

    for (int base = s; base < e; base += 128) {
        int n = min(128, e - base);
        if (tid < n) {
            int c = g_col[base + tid];
            ssrc[tid] = c;
            sw[tid]   = g_dinv[c] * di;
        }
        __syncthreads();
        int j = 0;
        for (; j + 8 <= n; j += 8) {
            float v0 = g_t[ssrc[j + 0] * DIM + tid];
            float v1 = g_t[ssrc[j + 1] * DIM + tid];
            float v2 = g_t[ssrc[j + 2] * DIM + tid];
            float v3 = g_t[ssrc[j + 3] * DIM + tid];
            float v4 = g_t[ssrc[j + 4] * DIM + tid];
            float v5 = g_t[ssrc[j + 5] * DIM + tid];
            float v6 = g_t[ssrc[j + 6] * DIM + tid];
            float v7 = g_t[ssrc[j + 7] * DIM + tid];
            acc = fmaf(sw[j + 0], v0, acc);
            acc = fmaf(sw[j + 1], v1, acc);
            acc = fmaf(sw[j + 2], v2, acc);
            acc = fmaf(sw[j + 3], v3, acc);
            acc = fmaf(sw[j + 4], v4, acc);
            acc = fmaf(sw[j + 5], v5, acc);
            acc = fmaf(sw[j + 6], v6, acc);
            acc = fmaf(sw[j + 7], v7, acc);
        }
        for (; j < n; ++j)
            acc = fmaf(sw[j], g_t[ssrc[j] * DIM + tid], acc);
        __syncthreads();
    }
    g_h[i * DIM + tid] = fmaxf(acc + bias[tid], 0.f);
}

// ---------------- mean pool (batch is sorted): segmented sums -------------
__global__ __launch_bounds__(128) void pool_kernel(const void* __restrict__ batch) {
    int n0  = blockIdx.x * 64;
    int tid = threadIdx.x;
    float acc = 0.f;
    int c = 0;
    int cur = load_idx(batch, n0);
    for (int n = n0; n < n0 + 64; ++n) {
        int g = load_idx(batch, n);
        if (g != cur) {
            atomicAdd(&g_gsum[cur * DIM + tid], acc);
            if (tid == 0) atomicAdd(&g_gcnt[cur], c);
            acc = 0.f; c = 0; cur = g;
        }
        acc += g_h[n * DIM + tid];
        ++c;
    }
    atomicAdd(&g_gsum[cur * DIM + tid], acc);
    if (tid == 0) atomicAdd(&g_gcnt[cur], c);
}

// ---------------- final: mean -> linear -> L2 normalize -------------------
__global__ __launch_bounds__(64) void final_kernel(const float* __restrict__ Wl,
                                                   const float* __restrict__ bl,
                                                   float* __restrict__ out) {
    int g = blockIdx.x, o = threadIdx.x;
    __shared__ float mean[DIM];
    __shared__ float red[OUTD];
    float cn = fmaxf((float)g_gcnt[g], 1.f);
    mean[o]      = g_gsum[g * DIM + o] / cn;
    mean[o + 64] = g_gsum[g * DIM + o + 64] / cn;
    __syncthreads();
    float acc = bl[o];
    #pragma unroll
    for (int h = 0; h < DIM; ++h)
        acc = fmaf(mean[h], Wl[h * OUTD + o], acc);
    red[o] = acc * acc;
    __syncthreads();
    for (int s = 32; s > 0; s >>= 1) {
        if (o < s) red[o] += red[o + s];
        __syncthreads();
    }
    float nrm = sqrtf(red[0]);
    out[g * OUTD + o] = acc / fmaxf(nrm, 1e-12f);
}

// ---------------- launch ----------------
extern "C" void kernel_launch(void* const* d_in, const int* in_sizes, int n_in,
                              void* d_out, int out_size) {
    const float* x     = (const float*)d_in[0];
    const float* W1    = (const float*)d_in[1];
    const float* b1    = (const float*)d_in[2];
    const float* W2    = (const float*)d_in[3];
    const float* b2    = (const float*)d_in[4];
    const float* Wl    = (const float*)d_in[5];
    const float* bl    = (const float*)d_in[6];
    const void*  ei    = d_in[7];
    const void*  batch = d_in[8];
    float* out = (float*)d_out;

    detect_kernel<<<1, 1>>>(ei);
    init_kernel<<<(N_NODES + 255) / 256, 256>>>();
    count_kernel<<<(N_EDGES + 511) / 512, 512>>>(ei);
    scan1_kernel<<<SCAN_B, 1024>>>();
    scan2_kernel<<<1, 64>>>();
    scan3_kernel<<<SCAN_B, 1024>>>();
    fill_kernel<<<(N_EDGES + 511) / 512, 512>>>(ei);

    // layer 1
    gemm_kernel<<<N_NODES / 64, 128>>>(x, W1);
    agg_kernel<<<N_NODES, 128>>>(b1);
    // layer 2
    gemm_kernel<<<N_NODES / 64, 128>>>(nullptr, W2);
    agg_kernel<<<N_NODES, 128>>>(b2);

    pool_kernel<<<N_NODES / 64, 128>>>(batch);
    final_kernel<<<NGRAPH, OUTD>>>(Wl, bl, out);
}

// round 4
// speedup vs baseline: 1.2990x; 1.1657x over previous
#include <cuda_runtime.h>
#include <math.h>

// Problem constants (fixed by the dataset)
#define N_NODES 40000
#define N_EDGES 640000
#define DIM     128
#define OUTD    64
#define NGRAPH  64
#define SCAN_B  40            // ceil(40000/1024)

// ---------------- device scratch (no allocation allowed) ----------------
__device__ float g_t[N_NODES * DIM];     // GEMM output (pre-aggregation features)
__device__ float g_h[N_NODES * DIM];     // layer output (post relu)
__device__ int   g_cnt[N_NODES];         // in-degree counts
__device__ int   g_rowptr[N_NODES + 1];  // CSR row pointers (by dst)
__device__ int   g_cursor[N_NODES];      // scatter cursors
__device__ int   g_col[N_EDGES];         // CSR col (src) indices
__device__ float g_dinv[N_NODES];        // 1/sqrt(deg+1)
__device__ float g_gsum[NGRAPH * DIM];   // pooled sums
__device__ int   g_gcnt[NGRAPH];         // nodes per graph
__device__ int   g_is64;                 // 1 if indices are int64, 0 if int32
__device__ int   g_bsum[SCAN_B];         // per-block sums for scan
__device__ int   g_boff[SCAN_B];         // exclusive block offsets

// Uniform index load honoring detected dtype.
__device__ __forceinline__ int load_idx(const void* p, int i) {
    if (g_is64) return (int)((const long long*)p)[i];
    return ((const int*)p)[i];
}

// ---------------- init (+ dtype detection by thread 0) ----------------
__global__ void init_kernel(const void* __restrict__ ei) {
    int i = blockIdx.x * blockDim.x + threadIdx.x;
    if (i == 0) {
        const long long* p = (const long long*)ei;
        int ok = 1;
        #pragma unroll
        for (int q = 0; q < 16; ++q) {
            long long v = p[q];
            if (v < 0 || v >= N_NODES) ok = 0;
        }
        g_is64 = ok;
    }
    if (i < N_NODES) g_cnt[i] = 0;
    if (i < NGRAPH * DIM) g_gsum[i] = 0.f;
    if (i < NGRAPH) g_gcnt[i] = 0;
}

// ---------------- degree count (in-degree at dst) ----------------
__global__ __launch_bounds__(512) void count_kernel(const void* __restrict__ ei) {
    int e = blockIdx.x * blockDim.x + threadIdx.x;
    if (e < N_EDGES) {
        int dst = load_idx(ei, N_EDGES + e);
        atomicAdd(&g_cnt[dst], 1);
    }
}

// ---------------- scan pass 1: per-block sums (40 blocks x 1024) ----------
__global__ __launch_bounds__(1024) void scan1_kernel() {
    __shared__ int wsum[32];
    int tid = threadIdx.x, lane = tid & 31, w = tid >> 5;
    int i = blockIdx.x * 1024 + tid;
    int v = (i < N_NODES) ? g_cnt[i] : 0;
    int s = v;
    #pragma unroll
    for (int off = 16; off > 0; off >>= 1)
        s += __shfl_down_sync(0xffffffffu, s, off);
    if (lane == 0) wsum[w] = s;
    __syncthreads();
    if (w == 0) {
        int t = wsum[lane];
        #pragma unroll
        for (int off = 16; off > 0; off >>= 1)
            t += __shfl_down_sync(0xffffffffu, t, off);
        if (lane == 0) g_bsum[blockIdx.x] = t;
    }
}

// ---------------- scan pass 2: exclusive scan of 40 block sums -----------
__global__ void scan2_kernel() {
    int tid = threadIdx.x;  // 64 threads
    int v = (tid < SCAN_B) ? g_bsum[tid] : 0;
    __shared__ int tmp[64];
    int lane = tid & 31, w = tid >> 5;
    int incl = v;
    #pragma unroll
    for (int off = 1; off < 32; off <<= 1) {
        int t = __shfl_up_sync(0xffffffffu, incl, off);
        if (lane >= off) incl += t;
    }
    tmp[tid] = incl;
    __syncthreads();
    int add = (w == 1) ? tmp[31] : 0;
    int excl = incl - v + add;
    if (tid < SCAN_B) g_boff[tid] = excl;
}

// ---------------- scan pass 3: block scan + offset, write CSR meta --------
__global__ __launch_bounds__(1024) void scan3_kernel() {
    __shared__ int wsum[32];
    int tid = threadIdx.x, lane = tid & 31, w = tid >> 5;
    int i = blockIdx.x * 1024 + tid;
    int v = (i < N_NODES) ? g_cnt[i] : 0;
    int incl = v;
    #pragma unroll
    for (int off = 1; off < 32; off <<= 1) {
        int t = __shfl_up_sync(0xffffffffu, incl, off);
        if (lane >= off) incl += t;
    }
    if (lane == 31) wsum[w] = incl;
    __syncthreads();
    if (w == 0) {
        int s = wsum[lane];
        #pragma unroll
        for (int off = 1; off < 32; off <<= 1) {
            int t = __shfl_up_sync(0xffffffffu, s, off);
            if (lane >= off) s += t;
        }
        wsum[lane] = s;
    }
    __syncthreads();
    int pref = (w > 0) ? wsum[w - 1] : 0;
    int inclTot = incl + pref + g_boff[blockIdx.x];
    if (i < N_NODES) {
        g_rowptr[i + 1] = inclTot;
        g_cursor[i] = inclTot - v;
        g_dinv[i] = rsqrtf((float)v + 1.0f);
        if (i == 0) g_rowptr[0] = 0;
    }
}

// ---------------- CSR fill: scatter src into per-dst slots ----------------
__global__ __launch_bounds__(512) void fill_kernel(const void* __restrict__ ei) {
    int e = blockIdx.x * blockDim.x + threadIdx.x;
    if (e < N_EDGES) {
        int src = load_idx(ei, e);
        int dst = load_idx(ei, N_EDGES + e);
        int pos = atomicAdd(&g_cursor[dst], 1);
        g_col[pos] = src;
    }
}

// ---------------- SGEMM: g_t = A(40000x128) @ W(128x128) ----------------
// Block tile 64x128, 128 threads, 8x8 microtile per thread.
__global__ __launch_bounds__(128) void gemm_kernel(const float* __restrict__ Ain,
                                                   const float* __restrict__ W) {
    const float* A = Ain ? Ain : g_h;
    __shared__ float As[32][68];    // [k][m], padded
    __shared__ float Bs[32][128];   // [k][n]

    int tid  = threadIdx.x;
    int tcol = tid & 15;   // 16 * TN(8) = 128 cols
    int trow = tid >> 4;   // 8  * TM(8) = 64 rows
    int row0 = blockIdx.x * 64;

    float acc[8][8];
    #pragma unroll
    for (int i = 0; i < 8; ++i)
        #pragma unroll
        for (int j = 0; j < 8; ++j) acc[i][j] = 0.f;

    for (int kt = 0; kt < 4; ++kt) {
        {
            int m  = tid >> 1;
            int k0 = (tid & 1) * 16;
            const float* ap = &A[(row0 + m) * DIM + kt * 32 + k0];
            #pragma unroll
            for (int q = 0; q < 4; ++q) {
                float4 a = *(const float4*)(ap + q * 4);
                As[k0 + q * 4 + 0][m] = a.x;
                As[k0 + q * 4 + 1][m] = a.y;
                As[k0 + q * 4 + 2][m] = a.z;
                As[k0 + q * 4 + 3][m] = a.w;
            }
        }
        #pragma unroll
        for (int i = 0; i < 8; ++i) {
            int f  = tid + i * 128;
            int kk = f >> 5;
            int nn = (f & 31) * 4;
            *(float4*)&Bs[kk][nn] = *(const float4*)&W[(kt * 32 + kk) * DIM + nn];
        }
        __syncthreads();

        #pragma unroll
        for (int k = 0; k < 32; ++k) {
            float4 a0 = *(const float4*)&As[k][trow * 8];
            float4 a1 = *(const float4*)&As[k][trow * 8 + 4];
            float4 b0 = *(const float4*)&Bs[k][tcol * 8];
            float4 b1 = *(const float4*)&Bs[k][tcol * 8 + 4];
            float av[8] = {a0.x, a0.y, a0.z, a0.w, a1.x, a1.y, a1.z, a1.w};
            float bv[8] = {b0.x, b0.y, b0.z, b0.w, b1.x, b1.y, b1.z, b1.w};
            #pragma unroll
            for (int i = 0; i < 8; ++i)
                #pragma unroll
                for (int j = 0; j < 8; ++j)
                    acc[i][j] = fmaf(av[i], bv[j], acc[i][j]);
        }
        __syncthreads();
    }

    #pragma unroll
    for (int i = 0; i < 8; ++i) {
        int r = row0 + trow * 8 + i;
        float4 c0 = make_float4(acc[i][0], acc[i][1], acc[i][2], acc[i][3]);
        float4 c1 = make_float4(acc[i][4], acc[i][5], acc[i][6], acc[i][7]);
        *(float4*)&g_t[r * DIM + tcol * 8]     = c0;
        *(float4*)&g_t[r * DIM + tcol * 8 + 4] = c1;
    }
}

// ---------------- aggregation: warp-per-node, float4 gathers --------------
// g_h[i] = relu(sum_j w_ij * g_t[src_j] + dinv_i^2 * g_t[i] + bias)
__global__ __launch_bounds__(256) void agg_kernel(const float* __restrict__ bias) {
    int warp = threadIdx.x >> 5;
    int lane = threadIdx.x & 31;
    int i = blockIdx.x * 8 + warp;           // 8 nodes per 256-thread block

    float di = g_dinv[i];
    const float4 tself = *(const float4*)&g_t[(size_t)i * DIM + lane * 4];
    float4 acc;
    acc.x = di * di * tself.x;
    acc.y = di * di * tself.y;
    acc.z = di * di * tself.z;
    acc.w = di * di * tself.w;

    int s = g_rowptr[i], e = g_rowptr[i + 1];
    for (int base = s; base < e; base += 32) {
        int n = min(32, e - base);
        int c = 0; float wgt = 0.f;
        if (lane < n) {
            c = g_col[base + lane];
            wgt = g_dinv[c] * di;
        }
        #pragma unroll 8
        for (int j = 0; j < n; ++j) {
            int   cj = __shfl_sync(0xffffffffu, c, j);
            float wj = __shfl_sync(0xffffffffu, wgt, j);
            const float4 v = *(const float4*)&g_t[(size_t)cj * DIM + lane * 4];
            acc.x = fmaf(wj, v.x, acc.x);
            acc.y = fmaf(wj, v.y, acc.y);
            acc.z = fmaf(wj, v.z, acc.z);
            acc.w = fmaf(wj, v.w, acc.w);
        }
    }

    const float4 b4 = *(const float4*)&bias[lane * 4];
    float4 r;
    r.x = fmaxf(acc.x + b4.x, 0.f);
    r.y = fmaxf(acc.y + b4.y, 0.f);
    r.z = fmaxf(acc.z + b4.z, 0.f);
    r.w = fmaxf(acc.w + b4.w, 0.f);
    *(float4*)&g_h[(size_t)i * DIM + lane * 4] = r;
}

// ---------------- mean pool (batch is sorted): segmented sums -------------
__global__ __launch_bounds__(128) void pool_kernel(const void* __restrict__ batch) {
    int n0  = blockIdx.x * 64;
    int tid = threadIdx.x;
    float acc = 0.f;
    int c = 0;
    int cur = load_idx(batch, n0);
    for (int n = n0; n < n0 + 64; ++n) {
        int g = load_idx(batch, n);
        if (g != cur) {
            atomicAdd(&g_gsum[cur * DIM + tid], acc);
            if (tid == 0) atomicAdd(&g_gcnt[cur], c);
            acc = 0.f; c = 0; cur = g;
        }
        acc += g_h[(size_t)n * DIM + tid];
        ++c;
    }
    atomicAdd(&g_gsum[cur * DIM + tid], acc);
    if (tid == 0) atomicAdd(&g_gcnt[cur], c);
}

// ---------------- final: mean -> linear -> L2 normalize -------------------
__global__ __launch_bounds__(64) void final_kernel(const float* __restrict__ Wl,
                                                   const float* __restrict__ bl,
                                                   float* __restrict__ out) {
    int g = blockIdx.x, o = threadIdx.x;
    __shared__ float mean[DIM];
    __shared__ float red[OUTD];
    float cn = fmaxf((float)g_gcnt[g], 1.f);
    mean[o]      = g_gsum[g * DIM + o] / cn;
    mean[o + 64] = g_gsum[g * DIM + o + 64] / cn;
    __syncthreads();
    float acc = bl[o];
    #pragma unroll
    for (int h = 0; h < DIM; ++h)
        acc = fmaf(mean[h], Wl[h * OUTD + o], acc);
    red[o] = acc * acc;
    __syncthreads();
    for (int s = 32; s > 0; s >>= 1) {
        if (o < s) red[o] += red[o + s];
        __syncthreads();
    }
    float nrm = sqrtf(red[0]);
    out[g * OUTD + o] = acc / fmaxf(nrm, 1e-12f);
}

// ---------------- launch ----------------
extern "C" void kernel_launch(void* const* d_in, const int* in_sizes, int n_in,
                              void* d_out, int out_size) {
    const float* x     = (const float*)d_in[0];
    const float* W1    = (const float*)d_in[1];
    const float* b1    = (const float*)d_in[2];
    const float* W2    = (const float*)d_in[3];
    const float* b2    = (const float*)d_in[4];
    const float* Wl    = (const float*)d_in[5];
    const float* bl    = (const float*)d_in[6];
    const void*  ei    = d_in[7];
    const void*  batch = d_in[8];
    float* out = (float*)d_out;

    init_kernel<<<(N_NODES + 255) / 256, 256>>>(ei);
    count_kernel<<<(N_EDGES + 511) / 512, 512>>>(ei);
    scan1_kernel<<<SCAN_B, 1024>>>();
    scan2_kernel<<<1, 64>>>();
    scan3_kernel<<<SCAN_B, 1024>>>();
    fill_kernel<<<(N_EDGES + 511) / 512, 512>>>(ei);

    // layer 1
    gemm_kernel<<<N_NODES / 64, 128>>>(x, W1);
    agg_kernel<<<N_NODES / 8, 256>>>(b1);
    // layer 2
    gemm_kernel<<<N_NODES / 64, 128>>>(nullptr, W2);
    agg_kernel<<<N_NODES / 8, 256>>>(b2);

    pool_kernel<<<N_NODES / 64, 128>>>(batch);
    final_kernel<<<NGRAPH, OUTD>>>(Wl, bl, out);
}